// round 17
// baseline (speedup 1.0000x reference)
#include <cuda_runtime.h>
#include <cuda_bf16.h>
#include <math.h>

#define Tt 128
#define Bb 32
#define PH 256
#define WH 1024
#define PV 45
#define WV 32000
#define PE 64
#define WE 512
#define GRID 128

// ---------------- device scratch (no allocations) ----------------
__device__ float g_Apos[Tt*Bb*4*PH];
__device__ float g_Aw0 [Tt*Bb*4*WH];
__device__ float g_ph  [(Tt+1)*Bb*PH];
__device__ float g_wh1 [(Tt+1)*Bb*WH];
__device__ float g_pc  [Bb*PH];
__device__ float g_wc0 [Bb*WH];
__device__ float g_wc1 [Bb*WH];
__device__ float g_wmid[Tt*Bb*WE];
__device__ __nv_bfloat16 g_embH[WV*WE];
__device__ __nv_bfloat16 g_embL[WV*WE];
__device__ __nv_bfloat16 g_midH[Tt*Bb*WE];
__device__ __nv_bfloat16 g_midL[Tt*Bb*WE];
// bf16 hi/lo weights for the recurrence cells
__device__ __nv_bfloat16 g_pWihH[4*PH*(PE+WH)], g_pWihL[4*PH*(PE+WH)];
__device__ __nv_bfloat16 g_pWhhH[4*PH*PH],      g_pWhhL[4*PH*PH];
__device__ __nv_bfloat16 g_w0WihH[4*WH*(WE+PH)], g_w0WihL[4*WH*(WE+PH)];
__device__ __nv_bfloat16 g_w0WhhH[4*WH*WH],     g_w0WhhL[4*WH*WH];
__device__ __nv_bfloat16 g_w1WihH[4*WH*WH],     g_w1WihL[4*WH*WH];
__device__ __nv_bfloat16 g_w1WhhH[4*WH*WH],     g_w1WhhL[4*WH*WH];
// bf16 hi/lo recurrent-state buffers (parity double-buffered)
__device__ __nv_bfloat16 g_phbH[2*Bb*PH],  g_phbL[2*Bb*PH];
__device__ __nv_bfloat16 g_wh0bH[2*Bb*WH], g_wh0bL[2*Bb*WH];
__device__ __nv_bfloat16 g_wh1bH[2*Bb*WH], g_wh1bL[2*Bb*WH];
__device__ unsigned g_cnt;
__device__ volatile unsigned g_gen;

// ---------------- generic helpers ----------------
__device__ __forceinline__ unsigned long long fma2(unsigned long long a,
                                                   unsigned long long b,
                                                   unsigned long long c) {
    unsigned long long d;
    asm("fma.rn.f32x2 %0, %1, %2, %3;" : "=l"(d) : "l"(a), "l"(b), "l"(c));
    return d;
}
__device__ __forceinline__ float acc_sum(unsigned long long v) {
    float x, y;
    asm("mov.b64 {%0,%1}, %2;" : "=f"(x), "=f"(y) : "l"(v));
    return x + y;
}
__device__ __forceinline__ float sigf(float x) { return 1.0f / (1.0f + expf(-x)); }

__device__ __forceinline__ void cp16(void* s, const void* g) {
    unsigned ss = (unsigned)__cvta_generic_to_shared(s);
    asm volatile("cp.async.cg.shared.global [%0], [%1], 16;" :: "r"(ss), "l"(g));
}
__device__ __forceinline__ void cp_commit() {
    asm volatile("cp.async.commit_group;" ::: "memory");
}
template <int N> __device__ __forceinline__ void cp_wait() {
    asm volatile("cp.async.wait_group %0;" :: "n"(N) : "memory");
}
__device__ __forceinline__ unsigned smem_u32(const void* p) {
    return (unsigned)__cvta_generic_to_shared(p);
}

// mma.sync bf16 + ldmatrix (non-arch-gated tensor path; verified in head_mma)
__device__ __forceinline__ void ldsm4(unsigned r[4], unsigned addr) {
    asm volatile("ldmatrix.sync.aligned.m8n8.x4.shared.b16 {%0,%1,%2,%3}, [%4];"
        : "=r"(r[0]), "=r"(r[1]), "=r"(r[2]), "=r"(r[3]) : "r"(addr));
}
__device__ __forceinline__ void ldsm2(unsigned r[2], unsigned addr) {
    asm volatile("ldmatrix.sync.aligned.m8n8.x2.shared.b16 {%0,%1}, [%2];"
        : "=r"(r[0]), "=r"(r[1]) : "r"(addr));
}
__device__ __forceinline__ void mma16816(float c[4], const unsigned a[4], const unsigned b[2]) {
    asm volatile("mma.sync.aligned.m16n8k16.row.col.f32.bf16.bf16.f32 "
        "{%0,%1,%2,%3}, {%4,%5,%6,%7}, {%8,%9}, {%0,%1,%2,%3};"
        : "+f"(c[0]), "+f"(c[1]), "+f"(c[2]), "+f"(c[3])
        : "r"(a[0]), "r"(a[1]), "r"(a[2]), "r"(a[3]), "r"(b[0]), "r"(b[1]));
}

// sense-reversing grid barrier (all GRID CTAs co-resident: 1 CTA/SM)
__device__ __forceinline__ void gsync() {
    __syncthreads();
    if (threadIdx.x == 0) {
        unsigned gen = g_gen;
        __threadfence();
        if (atomicAdd(&g_cnt, 1u) == GRID - 1u) {
            g_cnt = 0u;
            __threadfence();
            g_gen = gen + 1u;
        } else {
            while (g_gen == gen) { }
        }
        __threadfence();
    }
    __syncthreads();
}

// ---------------- init ----------------
__global__ void zero_init() {
    int i = blockIdx.x * blockDim.x + threadIdx.x;
    if (i == 0) { g_cnt = 0u; g_gen = 0u; }
    __nv_bfloat16 z = __float2bfloat16(0.f);
    if (i < Bb*PH) {
        g_pc[i] = 0.f;
        g_phbH[i] = z; g_phbL[i] = z;
    }
    if (i < Bb*WH) {
        g_wc0[i] = 0.f; g_wc1[i] = 0.f;
        g_wh0bH[i] = z; g_wh0bL[i] = z;
        g_wh1bH[i] = z; g_wh1bL[i] = z;
    }
}

// ---------------- fp32 -> bf16 hi/lo split ----------------
__global__ void cvt_hilo(const float* __restrict__ src,
                         __nv_bfloat16* __restrict__ hi,
                         __nv_bfloat16* __restrict__ lo, int n)
{
    int i = blockIdx.x * blockDim.x + threadIdx.x;
    if (i < n) {
        float v = src[i];
        __nv_bfloat16 h = __float2bfloat16(v);
        hi[i] = h;
        lo[i] = __float2bfloat16(v - __bfloat162float(h));
    }
}

// ---------------- 4-stage pipelined NT GEMM (fp32, precompute/wmid) ----------------
__global__ __launch_bounds__(256) void gemm_nt(
    const float* __restrict__ A, const int* __restrict__ gather, int lda,
    const float* __restrict__ Bm, int ldb,
    float* __restrict__ C, int ldc, int K,
    const float* __restrict__ bias1, const float* __restrict__ bias2)
{
    constexpr int S = 4;
    __shared__ __align__(16) float As[S][64][20];
    __shared__ __align__(16) float Bs[S][64][20];
    const int tid = threadIdx.x;
    const int m0 = blockIdx.y * 64, n0 = blockIdx.x * 64;
    const int tn = tid & 15, tm = tid >> 4;
    const int lrow = tid >> 2, lks = tid & 3;
    const int agr = gather ? gather[m0 + lrow] : (m0 + lrow);
    const float* aptr = A  + (size_t)agr * lda + lks * 4;
    const float* bptr = Bm + (size_t)(n0 + lrow) * ldb + lks * 4;

    unsigned long long acc[4][4];
#pragma unroll
    for (int r = 0; r < 4; r++)
#pragma unroll
        for (int s = 0; s < 4; s++) acc[r][s] = 0ull;

    const int nch = K >> 4;
#pragma unroll
    for (int i = 0; i < S - 1; i++) {
        if (i < nch) {
            cp16(&As[i][lrow][lks*4], aptr + i*16);
            cp16(&Bs[i][lrow][lks*4], bptr + i*16);
        }
        cp_commit();
    }

    for (int ci = 0; ci < nch; ci++) {
        if (ci + S - 1 < nch) {
            const int b = (ci + S - 1) & (S - 1);
            cp16(&As[b][lrow][lks*4], aptr + (ci + S - 1)*16);
            cp16(&Bs[b][lrow][lks*4], bptr + (ci + S - 1)*16);
            cp_commit();
            cp_wait<S-1>();
        } else {
            cp_wait<0>();
        }
        __syncthreads();
        const int bf = ci & (S - 1);
#pragma unroll
        for (int kk = 0; kk < 16; kk += 4) {
            ulonglong2 av[4], bv[4];
#pragma unroll
            for (int r = 0; r < 4; r++) av[r] = *(const ulonglong2*)&As[bf][tm*4 + r][kk];
#pragma unroll
            for (int s = 0; s < 4; s++) bv[s] = *(const ulonglong2*)&Bs[bf][tn + 16*s][kk];
#pragma unroll
            for (int r = 0; r < 4; r++)
#pragma unroll
                for (int s = 0; s < 4; s++) {
                    acc[r][s] = fma2(av[r].x, bv[s].x, acc[r][s]);
                    acc[r][s] = fma2(av[r].y, bv[s].y, acc[r][s]);
                }
        }
        __syncthreads();
    }
#pragma unroll
    for (int s = 0; s < 4; s++) {
        int n = n0 + tn + 16*s;
        float badd = 0.f;
        if (bias1) badd += bias1[n];
        if (bias2) badd += bias2[n];
#pragma unroll
        for (int r = 0; r < 4; r++) {
            int m = m0 + tm*4 + r;
            C[(size_t)m * ldc + n] = acc_sum(acc[r][s]) + badd;
        }
    }
}

// ---------------- bf16-split mma LSTM cell phase ----------------
// CTA owns 32 gate cols (8 h x 4 gates) x 32 batch rows. 8 warps = 8-way k-split,
// each warp does its k-region with m16n8k16 HMMA, 3-term hi/lo split, fp32 acc.
// smem per (stage, warp): XH/XL/WH/WL tiles, each [2 ksteps][32 rows][48B] = 12288 B.
// 48B row stride: 16B-aligned (cp.async/ldmatrix legal) and conflict-free
// (offsets mod 128 = {0,48,96,16,64,112,32,80}).
#define CROW 48
#define CBUF 3072            // one tile: 2*32*48
#define CWBLK 12288          // 4 tiles per (stage,warp)
__device__ __noinline__ void cell_phase_mma(
    float* smemf,
    const float* pre, const float* bih, const float* bhh,
    const __nv_bfloat16* x0h, const __nv_bfloat16* x0l, int ldx0,
    const __nv_bfloat16* W0h, const __nv_bfloat16* W0l, int ldW0, int K0,
    const __nv_bfloat16* x1h, const __nv_bfloat16* x1l, int ldx1,
    const __nv_bfloat16* W1h, const __nv_bfloat16* W1l, int ldW1, int K1,
    float* c_st, float* h_out_f,
    __nv_bfloat16* h_out_h, __nv_bfloat16* h_out_l, int H)
{
    const int cta = blockIdx.x;
    if (cta * 8 >= H) return;
    const int tid  = threadIdx.x;
    const int lane = tid & 31;
    const int wid  = tid >> 5;
    char* sb = (char*)smemf;
    const unsigned sbU = smem_u32(smemf);

    const int kspw  = ((K0 + K1) >> 4) >> 3;   // ksteps per warp
    const int iters = kspw >> 1;               // 2 ksteps per stage

    // preload pre/bias for pointwise (thread -> (b, h))
    const int pb = tid >> 3, phh = tid & 7;
    const int hmy = cta * 8 + phh;
    float pv[4];
#pragma unroll
    for (int gt = 0; gt < 4; gt++) {
        if (pre) pv[gt] = pre[(size_t)pb * (4*H) + gt*H + hmy];
        else     pv[gt] = bih[gt*H + hmy] + bhh[gt*H + hmy];
    }

    float acc[2][4][4];
#pragma unroll
    for (int mf = 0; mf < 2; mf++)
#pragma unroll
        for (int nf = 0; nf < 4; nf++)
#pragma unroll
            for (int i = 0; i < 4; i++) acc[mf][nf][i] = 0.f;

    auto load_stage = [&](int st, int cs) {
#pragma unroll
        for (int it = 0; it < 8; it++) {
            int i = tid + (it << 8);           // 0..2047
            int wslot = i >> 8;
            int rem = i & 255;
            int ks = rem >> 7;
            int rem2 = rem & 127;
            int which = rem2 >> 5;             // 0=xh 1=xl 2=wh 3=wl
            int row = rem2 & 31;
            int ci = wslot * kspw + cs*2 + ks;
            int kk = ci << 4;
            const __nv_bfloat16* src;
            if (which < 2) {
                if (kk < K0) src = (which ? x0l : x0h) + (size_t)row * ldx0 + kk;
                else         src = (which ? x1l : x1h) + (size_t)row * ldx1 + (kk - K0);
            } else {
                int j = (row >> 3) * H + cta * 8 + (row & 7);
                if (kk < K0) src = (which == 3 ? W0l : W0h) + (size_t)j * ldW0 + kk;
                else         src = (which == 3 ? W1l : W1h) + (size_t)j * ldW1 + (kk - K0);
            }
            char* dst = sb + (st*8 + wslot)*CWBLK + which*CBUF + ks*(32*CROW) + row*CROW;
            cp16(dst, src);
            cp16(dst + 16, src + 8);
        }
        cp_commit();
    };

    load_stage(0, 0);
    for (int cs = 0; cs < iters; cs++) {
        if (cs + 1 < iters) { load_stage((cs + 1) & 1, cs + 1); cp_wait<1>(); }
        else                { cp_wait<0>(); }
        __syncthreads();
        const int st = cs & 1;
        const unsigned blk = sbU + (unsigned)((st*8 + wid) * CWBLK);
        const int rowA = (lane & 7) + ((lane >> 3) & 1) * 8;
        const unsigned akoff = (unsigned)(lane >> 4) * 16u;
        const int browB = lane & 7;
        const unsigned bkoff = (unsigned)((lane >> 3) & 1) * 16u;
#pragma unroll
        for (int ks = 0; ks < 2; ks++) {
            const unsigned ksb = (unsigned)(ks * 32 * CROW);
            unsigned ah[2][4], al[2][4], bh[4][2], bl[4][2];
#pragma unroll
            for (int mf = 0; mf < 2; mf++) {
                unsigned ra = blk + ksb + (unsigned)((mf*16 + rowA) * CROW) + akoff;
                ldsm4(ah[mf], ra);
                ldsm4(al[mf], ra + (unsigned)CBUF);
            }
#pragma unroll
            for (int nf = 0; nf < 4; nf++) {
                unsigned rb = blk + 2u*CBUF + ksb + (unsigned)((nf*8 + browB) * CROW) + bkoff;
                ldsm2(bh[nf], rb);
                ldsm2(bl[nf], rb + (unsigned)CBUF);
            }
#pragma unroll
            for (int mf = 0; mf < 2; mf++)
#pragma unroll
                for (int nf = 0; nf < 4; nf++) {
                    mma16816(acc[mf][nf], ah[mf], bh[nf]);
                    mma16816(acc[mf][nf], ah[mf], bl[nf]);
                    mma16816(acc[mf][nf], al[mf], bh[nf]);
                }
        }
        __syncthreads();
    }

    // deterministic 8-way k-reduction through smem (stride 33), then pointwise
    float* red = smemf;    // overlay; mainloop ended with __syncthreads
#pragma unroll
    for (int mf = 0; mf < 2; mf++)
#pragma unroll
        for (int nf = 0; nf < 4; nf++)
#pragma unroll
            for (int i = 0; i < 4; i++) {
                int row = mf*16 + (lane >> 2) + ((i >> 1) << 3);
                int col = nf*8 + (lane & 3)*2 + (i & 1);
                red[(wid*32 + row)*33 + col] = acc[mf][nf][i];
            }
    __syncthreads();

    {
        float g4[4];
#pragma unroll
        for (int gt = 0; gt < 4; gt++) {
            int col = gt*8 + phh;
            float v = 0.f;
#pragma unroll
            for (int w = 0; w < 8; w++) v += red[(w*32 + pb)*33 + col];
            g4[gt] = v + pv[gt];
        }
        float cp = c_st[pb*H + hmy];
        float cn = sigf(g4[1]) * cp + sigf(g4[0]) * tanhf(g4[2]);
        c_st[pb*H + hmy] = cn;
        float hn = sigf(g4[3]) * tanhf(cn);
        int idx = pb*H + hmy;
        if (h_out_f) h_out_f[idx] = hn;
        __nv_bfloat16 hh16 = __float2bfloat16(hn);
        h_out_h[idx] = hh16;
        h_out_l[idx] = __float2bfloat16(hn - __bfloat162float(hh16));
    }
    __syncthreads();   // protect overlay before next phase's loads
}

// ---------------- persistent recurrence kernel ----------------
__global__ __launch_bounds__(256, 1) void recurrence(
    const float* __restrict__ pre_pos, const float* __restrict__ pre_w0,
    const float* __restrict__ w1bih, const float* __restrict__ w1bhh)
{
    extern __shared__ float smem[];
    for (int t = 0; t < Tt; t++) {
        const int rp = t & 1, wp = rp ^ 1;
        // pos: x0 = wh1(t-1), x1 = ph(t-1)
        cell_phase_mma(smem, pre_pos + (size_t)t * Bb * 4 * PH, nullptr, nullptr,
            g_wh1bH + rp*Bb*WH, g_wh1bL + rp*Bb*WH, WH, g_pWihH + PE, g_pWihL + PE, PE + WH, WH,
            g_phbH  + rp*Bb*PH, g_phbL  + rp*Bb*PH, PH, g_pWhhH,      g_pWhhL,      PH,      PH,
            g_pc, g_ph + (size_t)(t+1) * Bb * PH,
            g_phbH + wp*Bb*PH, g_phbL + wp*Bb*PH, PH);
        gsync();
        // w0: x0 = ph(new), x1 = wh0(t-1)
        cell_phase_mma(smem, pre_w0 + (size_t)t * Bb * 4 * WH, nullptr, nullptr,
            g_phbH  + wp*Bb*PH, g_phbL  + wp*Bb*PH, PH, g_w0WihH + WE, g_w0WihL + WE, WE + PH, PH,
            g_wh0bH + rp*Bb*WH, g_wh0bL + rp*Bb*WH, WH, g_w0WhhH,      g_w0WhhL,      WH,      WH,
            g_wc0, nullptr,
            g_wh0bH + wp*Bb*WH, g_wh0bL + wp*Bb*WH, WH);
        gsync();
        // w1: x0 = wh0(new), x1 = wh1(t-1)
        cell_phase_mma(smem, nullptr, w1bih, w1bhh,
            g_wh0bH + wp*Bb*WH, g_wh0bL + wp*Bb*WH, WH, g_w1WihH, g_w1WihL, WH, WH,
            g_wh1bH + rp*Bb*WH, g_wh1bL + rp*Bb*WH, WH, g_w1WhhH, g_w1WhhL, WH, WH,
            g_wc1, g_wh1 + (size_t)(t+1) * Bb * WH,
            g_wh1bH + wp*Bb*WH, g_wh1bL + wp*Bb*WH, WH);
        gsync();
    }
}

// ---------------- bf16 mma.sync head GEMM (verified R15) ----------------
#define HROW 40
__global__ __launch_bounds__(256) void head_mma(
    const __nv_bfloat16* __restrict__ Ah, const __nv_bfloat16* __restrict__ Al,
    const __nv_bfloat16* __restrict__ Bh, const __nv_bfloat16* __restrict__ Bl,
    const float* __restrict__ bias, float* __restrict__ C)
{
    extern __shared__ __align__(16) __nv_bfloat16 hsm[];
    const int tid = threadIdx.x, lane = tid & 31, wid = tid >> 5;
    const int wm = wid >> 2, wn = wid & 3;
    const int m0 = blockIdx.x * 128, n0 = blockIdx.y * 128;

    const __nv_bfloat16* srcs[4] = { Ah + (size_t)m0 * WE, Al + (size_t)m0 * WE,
                                     Bh + (size_t)n0 * WE, Bl + (size_t)n0 * WE };

    float acc[4][4][4];
#pragma unroll
    for (int mf = 0; mf < 4; mf++)
#pragma unroll
        for (int nf = 0; nf < 4; nf++)
#pragma unroll
            for (int i = 0; i < 4; i++) acc[mf][nf][i] = 0.f;

    auto tile = [&](int st, int typ) -> __nv_bfloat16* {
        return hsm + (size_t)(st*4 + typ) * 128 * HROW;
    };
    auto load_stage = [&](int st, int kc) {
#pragma unroll
        for (int i = 0; i < 8; i++) {
            int idx = tid + (i << 8);
            int typ = idx >> 9;
            int rem = idx & 511;
            int row = rem >> 2, unit = rem & 3;
            cp16(tile(st, typ) + row*HROW + unit*8,
                 srcs[typ] + (size_t)row * WE + kc*32 + unit*8);
        }
        cp_commit();
    };

    load_stage(0, 0);
    for (int kc = 0; kc < 16; kc++) {
        if (kc + 1 < 16) { load_stage((kc + 1) & 1, kc + 1); cp_wait<1>(); }
        else             { cp_wait<0>(); }
        __syncthreads();
        const int st = kc & 1;
        const unsigned aAh = smem_u32(tile(st, 0));
        const unsigned aAl = smem_u32(tile(st, 1));
        const unsigned aBh = smem_u32(tile(st, 2));
        const unsigned aBl = smem_u32(tile(st, 3));
#pragma unroll
        for (int ks = 0; ks < 2; ks++) {
            const int arow = wm*64 + (lane & 7) + ((lane >> 3) & 1) * 8;
            const unsigned aoff = (unsigned)(ks*2 + (lane >> 4)) * 16u;
            const int brow = wn*32 + (lane & 7);
            const unsigned boff = (unsigned)(ks*2 + ((lane >> 3) & 1)) * 16u;
            unsigned ah[4][4], al[4][4];
#pragma unroll
            for (int mf = 0; mf < 4; mf++) {
                ldsm4(ah[mf], aAh + (unsigned)(arow + mf*16) * (HROW*2) + aoff);
                ldsm4(al[mf], aAl + (unsigned)(arow + mf*16) * (HROW*2) + aoff);
            }
            unsigned bh[4][2], bl[4][2];
#pragma unroll
            for (int nf = 0; nf < 4; nf++) {
                ldsm2(bh[nf], aBh + (unsigned)(brow + nf*8) * (HROW*2) + boff);
                ldsm2(bl[nf], aBl + (unsigned)(brow + nf*8) * (HROW*2) + boff);
            }
#pragma unroll
            for (int mf = 0; mf < 4; mf++)
#pragma unroll
                for (int nf = 0; nf < 4; nf++) {
                    mma16816(acc[mf][nf], ah[mf], bh[nf]);
                    mma16816(acc[mf][nf], ah[mf], bl[nf]);
                    mma16816(acc[mf][nf], al[mf], bh[nf]);
                }
        }
        __syncthreads();
    }

#pragma unroll
    for (int mf = 0; mf < 4; mf++) {
        const int r0 = m0 + wm*64 + mf*16 + (lane >> 2);
#pragma unroll
        for (int nf = 0; nf < 4; nf++) {
            const int c0 = n0 + wn*32 + nf*8 + (lane & 3)*2;
            const float b0 = bias[c0], b1 = bias[c0+1];
            float2 v0 = make_float2(acc[mf][nf][0] + b0, acc[mf][nf][1] + b1);
            float2 v1 = make_float2(acc[mf][nf][2] + b0, acc[mf][nf][3] + b1);
            *(float2*)&C[(size_t)r0 * WV + c0]       = v0;
            *(float2*)&C[(size_t)(r0 + 8) * WV + c0] = v1;
        }
    }
}

// ---------------- pos head: Linear(256->45) + log-softmax ----------------
__global__ void pos_head(const float* __restrict__ pouts,
                         const float* __restrict__ W, const float* __restrict__ bias,
                         float* __restrict__ out)
{
    __shared__ float sv[64];
    __shared__ float sred[2];
    int r = blockIdx.x, jt = threadIdx.x;
    const float* x = pouts + (size_t)r * PH;
    float v = 0.f;
    if (jt < PV) {
        float s = bias[jt];
        const float* w = W + (size_t)jt * PH;
#pragma unroll 4
        for (int k = 0; k < PH; k++) s += x[k] * w[k];
        v = s;
    }
    sv[jt] = v;
    __syncthreads();
    if (jt == 0) {
        float m = sv[0];
        for (int i = 1; i < PV; i++) m = fmaxf(m, sv[i]);
        float sum = 0.f;
        for (int i = 0; i < PV; i++) sum += expf(sv[i] - m);
        sred[0] = m; sred[1] = logf(sum);
    }
    __syncthreads();
    if (jt < PV) out[(size_t)r * PV + jt] = v - sred[0] - sred[1];
}

// ---------------- word log-softmax in place (vectorized) ----------------
__global__ __launch_bounds__(512) void wlogsoftmax(float* __restrict__ w)
{
    __shared__ float red[512];
    int r = blockIdx.x, tid = threadIdx.x;
    float4* row = (float4*)(w + (size_t)r * WV);
    const int NV = WV / 4;
    float m = -1e30f;
    for (int i = tid; i < NV; i += 512) {
        float4 v = row[i];
        m = fmaxf(m, fmaxf(fmaxf(v.x, v.y), fmaxf(v.z, v.w)));
    }
    red[tid] = m; __syncthreads();
    for (int s = 256; s > 0; s >>= 1) { if (tid < s) red[tid] = fmaxf(red[tid], red[tid+s]); __syncthreads(); }
    m = red[0]; __syncthreads();
    float sum = 0.f;
    for (int i = tid; i < NV; i += 512) {
        float4 v = row[i];
        sum += expf(v.x - m) + expf(v.y - m) + expf(v.z - m) + expf(v.w - m);
    }
    red[tid] = sum; __syncthreads();
    for (int s = 256; s > 0; s >>= 1) { if (tid < s) red[tid] += red[tid+s]; __syncthreads(); }
    float lg = m + logf(red[0]);
    for (int i = tid; i < NV; i += 512) {
        float4 v = row[i];
        v.x -= lg; v.y -= lg; v.z -= lg; v.w -= lg;
        row[i] = v;
    }
}

// ---------------- launch ----------------
extern "C" void kernel_launch(void* const* d_in, const int* in_sizes, int n_in,
                              void* d_out, int out_size)
{
    const int*   pos      = (const int*)d_in[0];
    const int*   word     = (const int*)d_in[1];
    const float* pos_emb  = (const float*)d_in[2];
    const float* word_emb = (const float*)d_in[3];
    const float* pWih     = (const float*)d_in[4];
    const float* pWhh     = (const float*)d_in[5];
    const float* pbih     = (const float*)d_in[6];
    const float* pbhh     = (const float*)d_in[7];
    const float* w0Wih    = (const float*)d_in[8];
    const float* w0Whh    = (const float*)d_in[9];
    const float* w0bih    = (const float*)d_in[10];
    const float* w0bhh    = (const float*)d_in[11];
    const float* w1Wih    = (const float*)d_in[12];
    const float* w1Whh    = (const float*)d_in[13];
    const float* w1bih    = (const float*)d_in[14];
    const float* w1bhh    = (const float*)d_in[15];
    const float* pprojW   = (const float*)d_in[16];
    const float* pprojb   = (const float*)d_in[17];
    const float* wp1W     = (const float*)d_in[18];
    const float* wp1b     = (const float*)d_in[19];
    const float* wp2b     = (const float*)d_in[20];

    float *pA, *pA0, *ph, *wh1, *wmid;
    __nv_bfloat16 *embH, *embL, *midH, *midL;
    cudaGetSymbolAddress((void**)&pA,   g_Apos);
    cudaGetSymbolAddress((void**)&pA0,  g_Aw0);
    cudaGetSymbolAddress((void**)&ph,   g_ph);
    cudaGetSymbolAddress((void**)&wh1,  g_wh1);
    cudaGetSymbolAddress((void**)&wmid, g_wmid);
    cudaGetSymbolAddress((void**)&embH, g_embH);
    cudaGetSymbolAddress((void**)&embL, g_embL);
    cudaGetSymbolAddress((void**)&midH, g_midH);
    cudaGetSymbolAddress((void**)&midL, g_midL);

    __nv_bfloat16 *pWihH, *pWihL, *pWhhH, *pWhhL, *w0WihH, *w0WihL, *w0WhhH, *w0WhhL;
    __nv_bfloat16 *w1WihH, *w1WihL, *w1WhhH, *w1WhhL;
    cudaGetSymbolAddress((void**)&pWihH,  g_pWihH);  cudaGetSymbolAddress((void**)&pWihL,  g_pWihL);
    cudaGetSymbolAddress((void**)&pWhhH,  g_pWhhH);  cudaGetSymbolAddress((void**)&pWhhL,  g_pWhhL);
    cudaGetSymbolAddress((void**)&w0WihH, g_w0WihH); cudaGetSymbolAddress((void**)&w0WihL, g_w0WihL);
    cudaGetSymbolAddress((void**)&w0WhhH, g_w0WhhH); cudaGetSymbolAddress((void**)&w0WhhL, g_w0WhhL);
    cudaGetSymbolAddress((void**)&w1WihH, g_w1WihH); cudaGetSymbolAddress((void**)&w1WihL, g_w1WihL);
    cudaGetSymbolAddress((void**)&w1WhhH, g_w1WhhH); cudaGetSymbolAddress((void**)&w1WhhL, g_w1WhhL);

    const int smem_rec = 2 * 8 * CWBLK;                  // 196608 B
    cudaFuncSetAttribute(recurrence, cudaFuncAttributeMaxDynamicSharedMemorySize, smem_rec);
    const int smem_head = 2 * 4 * 128 * HROW * 2;        // 81920 B
    cudaFuncSetAttribute(head_mma, cudaFuncAttributeMaxDynamicSharedMemorySize, smem_head);

    zero_init<<<(Bb*WH + 255) / 256, 256>>>();

    // precompute input projections (+ both biases) for all (t,b) rows
    gemm_nt<<<dim3(4*PH/64, Tt*Bb/64), 256>>>(pos_emb, pos, PE, pWih, PE+WH,
                                              pA, 4*PH, PE, pbih, pbhh);
    gemm_nt<<<dim3(4*WH/64, Tt*Bb/64), 256>>>(word_emb, word, WE, w0Wih, WE+PH,
                                              pA0, 4*WH, WE, w0bih, w0bhh);

    // bf16 hi/lo weight + embedding splits
    cvt_hilo<<<(4*PH*(PE+WH) + 255)/256, 256>>>(pWih,  pWihH,  pWihL,  4*PH*(PE+WH));
    cvt_hilo<<<(4*PH*PH      + 255)/256, 256>>>(pWhh,  pWhhH,  pWhhL,  4*PH*PH);
    cvt_hilo<<<(4*WH*(WE+PH) + 255)/256, 256>>>(w0Wih, w0WihH, w0WihL, 4*WH*(WE+PH));
    cvt_hilo<<<(4*WH*WH      + 255)/256, 256>>>(w0Whh, w0WhhH, w0WhhL, 4*WH*WH);
    cvt_hilo<<<(4*WH*WH      + 255)/256, 256>>>(w1Wih, w1WihH, w1WihL, 4*WH*WH);
    cvt_hilo<<<(4*WH*WH      + 255)/256, 256>>>(w1Whh, w1WhhH, w1WhhL, 4*WH*WH);
    cvt_hilo<<<(WV*WE + 255)/256, 256>>>(word_emb, embH, embL, WV*WE);

    // whole recurrence in one persistent kernel (bf16-split mma cells)
    recurrence<<<GRID, 256, smem_rec>>>(pA, pA0, w1bih, w1bhh);

    float* out  = (float*)d_out;
    float* wout = out + (size_t)Tt * Bb * PV;

    // w_mid = w_outs @ wp1_W^T + wp1_b  (fp32), then hi/lo split
    gemm_nt<<<dim3(WE/64, Tt*Bb/64), 256>>>(wh1 + (size_t)Bb * WH, nullptr, WH,
                                            wp1W, WH, wmid, WE, WH, wp1b, nullptr);
    cvt_hilo<<<(Tt*Bb*WE + 255)/256, 256>>>(wmid, midH, midL, Tt*Bb*WE);

    // word logits via bf16-split mma.sync GEMM, directly into d_out
    head_mma<<<dim3(Tt*Bb/128, WV/128), 256, smem_head>>>(midH, midL, embH, embL,
                                                          wp2b, wout);

    // pos head (fused log-softmax)
    pos_head<<<Tt*Bb, 64>>>(ph + (size_t)Bb * PH, pprojW, pprojb, out);
    // word log-softmax in place
    wlogsoftmax<<<Tt*Bb, 512>>>(wout);
}